// round 4
// baseline (speedup 1.0000x reference)
#include <cuda_runtime.h>
#include <cuda_bf16.h>
#include <cstdint>

#define KDIM 4096
#define MDIM 4096   // B*S = 4*1024
#define NDIM 4096

// ---------------- device scratch (static allocation — allowed) ----------------
__device__ __nv_bfloat16 g_xhi[(size_t)MDIM * KDIM];
__device__ __nv_bfloat16 g_xlo[(size_t)MDIM * KDIM];
__device__ __nv_bfloat16 g_wq [(size_t)NDIM * KDIM];
__device__ float         g_rowsum[MDIM];

// ---------------- prep: x -> bf16 hi/lo split + row sums ----------------
__global__ void prep_x_kernel(const float* __restrict__ x)
{
    int m   = blockIdx.x;
    int tid = threadIdx.x;                       // 128 threads
    const float4* xr = (const float4*)(x + (size_t)m * KDIM);
    uint2* hi = (uint2*)(g_xhi + (size_t)m * KDIM);
    uint2* lo = (uint2*)(g_xlo + (size_t)m * KDIM);
    float s = 0.f;
    for (int i = tid; i < KDIM / 4; i += 128) {
        float4 v = xr[i];
        s += (v.x + v.y) + (v.z + v.w);
        __nv_bfloat162 h01 = __floats2bfloat162_rn(v.x, v.y);
        __nv_bfloat162 h23 = __floats2bfloat162_rn(v.z, v.w);
        __nv_bfloat162 l01 = __floats2bfloat162_rn(v.x - __low2float(h01), v.y - __high2float(h01));
        __nv_bfloat162 l23 = __floats2bfloat162_rn(v.z - __low2float(h23), v.w - __high2float(h23));
        uint2 hb, lb;
        hb.x = *(uint32_t*)&h01; hb.y = *(uint32_t*)&h23;
        lb.x = *(uint32_t*)&l01; lb.y = *(uint32_t*)&l23;
        hi[i] = hb; lo[i] = lb;
    }
    __shared__ float red[4];
    #pragma unroll
    for (int o = 16; o > 0; o >>= 1) s += __shfl_xor_sync(0xffffffffu, s, o);
    if ((tid & 31) == 0) red[tid >> 5] = s;
    __syncthreads();
    if (tid == 0) g_rowsum[m] = (red[0] + red[1]) + (red[2] + red[3]);
}

// ---------------- prep: int32 qweight -> bf16 (values 0..255 are exact) ----------------
__global__ void prep_w_kernel(const int* __restrict__ q)
{
    size_t i = (size_t)blockIdx.x * blockDim.x + threadIdx.x;   // one int4 each
    int4 v = ((const int4*)q)[i];
    __nv_bfloat162 a = __floats2bfloat162_rn((float)v.x, (float)v.y);
    __nv_bfloat162 b = __floats2bfloat162_rn((float)v.z, (float)v.w);
    uint2 o; o.x = *(uint32_t*)&a; o.y = *(uint32_t*)&b;
    ((uint2*)g_wq)[i] = o;
}

// ---------------- GEMM config ----------------
constexpr int BM = 128;
constexpr int BN = 256;
constexpr int BK = 32;                      // bf16 elems per k-tile (64B of data per row)
constexpr int KT = KDIM / BK;               // 128
constexpr int STAGES = 4;
constexpr int PITCH = 80;                   // 64B data + 16B pad: conflict-free ldmatrix
constexpr int A_T_BYTES = BM * PITCH;       // 10240 (one of hi/lo)
constexpr int B_T_BYTES = BN * PITCH;       // 20480
constexpr int OFF_ALO = A_T_BYTES;          // 10240
constexpr int OFF_B   = 2 * A_T_BYTES;      // 20480
constexpr int STAGE_BYTES = 2 * A_T_BYTES + B_T_BYTES;   // 40960
constexpr int SMEM_TOTAL  = STAGES * STAGE_BYTES;        // 163840

// ---------------- PTX helpers (sm_80-portable only — no 'a' features) ----------------
__device__ __forceinline__ uint32_t smem_u32(const void* p) {
    uint32_t a;
    asm("{ .reg .u64 t; cvta.to.shared.u64 t, %1; cvt.u32.u64 %0, t; }" : "=r"(a) : "l"(p));
    return a;
}
__device__ __forceinline__ void cp_async16(uint32_t s, const void* g) {
    asm volatile("cp.async.cg.shared.global [%0], [%1], 16;" :: "r"(s), "l"(g) : "memory");
}
__device__ __forceinline__ void cp_commit() { asm volatile("cp.async.commit_group;" ::: "memory"); }
template <int N> __device__ __forceinline__ void cp_wait() {
    asm volatile("cp.async.wait_group %0;" :: "n"(N) : "memory");
}
__device__ __forceinline__ void ldsm4(uint32_t* r, uint32_t addr) {
    asm volatile("ldmatrix.sync.aligned.m8n8.x4.shared.b16 {%0,%1,%2,%3}, [%4];"
                 : "=r"(r[0]), "=r"(r[1]), "=r"(r[2]), "=r"(r[3]) : "r"(addr));
}
__device__ __forceinline__ void mma16816(float* c, const uint32_t* a, uint32_t b0, uint32_t b1) {
    asm volatile("mma.sync.aligned.m16n8k16.row.col.f32.bf16.bf16.f32 "
                 "{%0,%1,%2,%3}, {%4,%5,%6,%7}, {%8,%9}, {%0,%1,%2,%3};"
                 : "+f"(c[0]), "+f"(c[1]), "+f"(c[2]), "+f"(c[3])
                 : "r"(a[0]), "r"(a[1]), "r"(a[2]), "r"(a[3]), "r"(b0), "r"(b1));
}

// ---------------- tile loads: 2048 x 16B chunks / 512 threads = 4 each ----------------
__device__ __forceinline__ void issue_tile(int tid, int tm, int tn, int kt, uint32_t sbase)
{
    // A hi + lo: 128 rows x 4 chunks each
    int r = tid >> 2, c = tid & 3;
    size_t gofs = (size_t)r * KDIM + (size_t)kt * BK + c * 8;   // bf16 elements
    uint32_t so = (uint32_t)(r * PITCH + c * 16);
    cp_async16(sbase + so,           g_xhi + (size_t)tm * BM * KDIM + gofs);
    cp_async16(sbase + OFF_ALO + so, g_xlo + (size_t)tm * BM * KDIM + gofs);
    // B: 256 rows x 4 chunks = 1024 chunks, 2 per thread
    #pragma unroll
    for (int i = 0; i < 2; i++) {
        int ch = tid + i * 512;
        int rb = ch >> 2, cb = ch & 3;
        cp_async16(sbase + OFF_B + (uint32_t)(rb * PITCH + cb * 16),
                   g_wq + (size_t)(tn * BN + rb) * KDIM + (size_t)kt * BK + cb * 8);
    }
}

// ---------------- main GEMM: acc = Ahi*B^T + Alo*B^T (fp32 accum), fused dequant ----------------
__global__ void __launch_bounds__(512, 1) gemm_kernel(
    float* __restrict__ out,
    const float* __restrict__ scales,
    const int*   __restrict__ zps,
    const float* __restrict__ bias)
{
    extern __shared__ __align__(128) uint8_t smem_buf[];
    const uint32_t smem_base = smem_u32(smem_buf);
    const int tid = threadIdx.x, wid = tid >> 5, lane = tid & 31;
    const int warp_m = wid & 3, warp_n = wid >> 2;          // 4 x 4 warps, 32 x 64 each
    const int lane16 = lane & 15, laneHi = lane >> 4;

    // L2-friendly rasterization: groups of 8 m-tiles, tile_m fastest
    constexpr int NTM = MDIM / BM, NTN = NDIM / BN, GROUP_M = 8;
    int pid = blockIdx.x;
    int nig = GROUP_M * NTN;
    int first_m = (pid / nig) * GROUP_M;
    int gsz = (NTM - first_m < GROUP_M) ? (NTM - first_m) : GROUP_M;
    int tile_m = first_m + (pid % gsz);
    int tile_n = (pid % nig) / gsz;

    // per-lane ldmatrix offsets within a stage
    const uint32_t offA = (uint32_t)((warp_m * 32 + lane16) * PITCH + laneHi * 16);
    const uint32_t offB = (uint32_t)(OFF_B + (warp_n * 64 + lane16) * PITCH + laneHi * 16);

    float acc[2][8][4];
    #pragma unroll
    for (int i = 0; i < 2; i++)
        #pragma unroll
        for (int j = 0; j < 8; j++)
            #pragma unroll
            for (int k = 0; k < 4; k++) acc[i][j][k] = 0.f;

    // prologue: prefetch stages 0..STAGES-2
    #pragma unroll
    for (int s = 0; s < STAGES - 1; s++) {
        issue_tile(tid, tile_m, tile_n, s, smem_base + s * STAGE_BYTES);
        cp_commit();
    }

    for (int kt = 0; kt < KT; kt++) {
        cp_wait<STAGES - 2>();               // stage kt resident
        __syncthreads();                     // also: stage kt-1 buffer now reusable

        int pf = kt + STAGES - 1;            // prefetch into (kt-1)%STAGES buffer
        if (pf < KT) issue_tile(tid, tile_m, tile_n, pf, smem_base + (pf % STAGES) * STAGE_BYTES);
        cp_commit();                         // commit (possibly empty) keeps accounting

        const uint32_t sb  = smem_base + (kt % STAGES) * STAGE_BYTES;
        const uint32_t aHi = sb + offA;
        const uint32_t aLo = aHi + OFF_ALO;
        const uint32_t bAd = sb + offB;

        #pragma unroll
        for (int ks = 0; ks < 2; ks++) {     // two K=16 steps per BK=32
            uint32_t ah[2][4], al[2][4], bb[4][4];
            ldsm4(ah[0], aHi + ks * 32);
            ldsm4(ah[1], aHi + 1280 + ks * 32);        // +16 rows * 80B
            ldsm4(al[0], aLo + ks * 32);
            ldsm4(al[1], aLo + 1280 + ks * 32);
            #pragma unroll
            for (int p = 0; p < 4; p++) ldsm4(bb[p], bAd + p * 1280 + ks * 32);
            // all-hi then all-lo: 16 independent accumulators each -> good ILP
            #pragma unroll
            for (int mt = 0; mt < 2; mt++)
                #pragma unroll
                for (int p = 0; p < 4; p++) {
                    mma16816(acc[mt][2 * p],     ah[mt], bb[p][0], bb[p][2]);
                    mma16816(acc[mt][2 * p + 1], ah[mt], bb[p][1], bb[p][3]);
                }
            #pragma unroll
            for (int mt = 0; mt < 2; mt++)
                #pragma unroll
                for (int p = 0; p < 4; p++) {
                    mma16816(acc[mt][2 * p],     al[mt], bb[p][0], bb[p][2]);
                    mma16816(acc[mt][2 * p + 1], al[mt], bb[p][1], bb[p][3]);
                }
        }
    }

    // ---------------- epilogue: Y = s*(G - zp*rowsum) + b ----------------
    const int gr = lane >> 2, gc = lane & 3;
    #pragma unroll
    for (int mt = 0; mt < 2; mt++) {
        int r0 = tile_m * BM + warp_m * 32 + mt * 16 + gr;
        float rs0 = g_rowsum[r0];
        float rs1 = g_rowsum[r0 + 8];
        float* o0 = out + (size_t)r0 * NDIM;
        float* o1 = o0 + (size_t)8 * NDIM;
        #pragma unroll
        for (int nt = 0; nt < 8; nt++) {
            int col = tile_n * BN + warp_n * 64 + nt * 8 + gc * 2;
            float2 sc = *(const float2*)(scales + col);
            int2   zp = *(const int2*)(zps + col);
            float2 bi = *(const float2*)(bias + col);
            const float* a = acc[mt][nt];
            float2 v0, v1;
            v0.x = fmaf(sc.x, a[0] - (float)zp.x * rs0, bi.x);
            v0.y = fmaf(sc.y, a[1] - (float)zp.y * rs0, bi.y);
            v1.x = fmaf(sc.x, a[2] - (float)zp.x * rs1, bi.x);
            v1.y = fmaf(sc.y, a[3] - (float)zp.y * rs1, bi.y);
            *(float2*)(o0 + col) = v0;
            *(float2*)(o1 + col) = v1;
        }
    }
}

// ---------------- launch ----------------
extern "C" void kernel_launch(void* const* d_in, const int* in_sizes, int n_in,
                              void* d_out, int out_size)
{
    const float* x      = (const float*)d_in[0];
    const int*   qw     = (const int*)  d_in[1];
    const float* scales = (const float*)d_in[2];
    const int*   zps    = (const int*)  d_in[3];
    const float* bias   = (const float*)d_in[4];
    float* out = (float*)d_out;

    prep_x_kernel<<<MDIM, 128>>>(x);
    prep_w_kernel<<<(int)(((size_t)NDIM * KDIM / 4) / 256), 256>>>(qw);

    cudaFuncSetAttribute(gemm_kernel, cudaFuncAttributeMaxDynamicSharedMemorySize, SMEM_TOTAL);
    gemm_kernel<<<(MDIM / BM) * (NDIM / BN), 512, SMEM_TOTAL>>>(out, scales, zps, bias);
}